// round 17
// baseline (speedup 1.0000x reference)
#include <cuda_runtime.h>
#include <cuda_fp16.h>
#include <math.h>
#include <stdint.h>

#define N_NODES 32768
#define N_EDGES 524288
#define FT_IN   256
#define HID     128
#define DHID    129        // HID+1
#define BATCH   64
#define NPB     512        // N_NODES / BATCH
#define EPSV    1e-7f
#define CAP     96         // per-node bucket capacity (mean deg 16, sigma 4)

// ---------------- scratch (device globals; no runtime allocation) ----------
__device__ uint32_t g_xsh[N_NODES * (FT_IN / 2)]; // fp16 pairs: logmap0(x)
__device__ uint32_t g_th[N_NODES * (HID / 2)];    // fp16 pairs: tangent (gelu'd)
__device__ float    g_z[N_NODES * HID];           // z fp32 (gather table)
__device__ float g_ssrc[N_NODES];
__device__ float g_sdst[N_NODES];
__device__ float g_h2[N_NODES * DHID];    // after layer-2 (hyperboloid)
// bucketed adjacency by dst (built once per call, reused by both layers)
__device__ int   g_cnt[N_NODES];          // per-node edge count
__device__ int   g_buck[N_NODES * CAP];   // src ids, node-major buckets

// ---------------- helpers --------------------------------------------------
__device__ __forceinline__ float warp_sum(float v) {
    #pragma unroll
    for (int o = 16; o > 0; o >>= 1) v += __shfl_xor_sync(0xFFFFFFFFu, v, o);
    return v;
}
__device__ __forceinline__ float gelu_tanh(float t) {
    float t3 = t * t * t;
    return 0.5f * t * (1.0f + tanhf(0.7978845608028654f * (t + 0.044715f * t3)));
}
__device__ __forceinline__ uint32_t pack_h2(float lo, float hi) {
    __half2 h = __floats2half2_rn(lo, hi);
    return *(uint32_t*)&h;
}
__device__ __forceinline__ void mma_f16(float c[4], uint32_t a0, uint32_t a1,
                                        uint32_t a2, uint32_t a3,
                                        uint32_t b0, uint32_t b1) {
    asm volatile(
        "mma.sync.aligned.m16n8k16.row.col.f32.f16.f16.f32 "
        "{%0,%1,%2,%3}, {%4,%5,%6,%7}, {%8,%9}, {%0,%1,%2,%3};"
        : "+f"(c[0]), "+f"(c[1]), "+f"(c[2]), "+f"(c[3])
        : "r"(a0), "r"(a1), "r"(a2), "r"(a3), "r"(b0), "r"(b1));
}
// packed dual-fp32 FMA (sm_100+): acc (f32x2) += z (f32x2) * w (f32x2)
__device__ __forceinline__ void fma_x2(unsigned long long& acc,
                                       unsigned long long z,
                                       unsigned long long w) {
    asm("fma.rn.f32x2 %0, %1, %2, %0;" : "+l"(acc) : "l"(z), "l"(w));
}
__device__ __forceinline__ unsigned long long dupw(float w) {
    unsigned long long r;
    asm("mov.b64 %0, {%1, %1};" : "=l"(r) : "f"(w));
    return r;
}

// ---------------- one-pass bucketed adjacency build -------------------------
__global__ void k_scatter(const int* __restrict__ ei) {
    int i = blockIdx.x * blockDim.x + threadIdx.x;     // i < N_EDGES/4
    int4 d = ((const int4*)ei)[i];
    int4 s = ((const int4*)(ei + N_EDGES))[i];
    int p;
    p = atomicAdd(&g_cnt[d.x], 1); g_buck[d.x * CAP + p] = s.x;
    p = atomicAdd(&g_cnt[d.y], 1); g_buck[d.y * CAP + p] = s.y;
    p = atomicAdd(&g_cnt[d.z], 1); g_buck[d.z * CAP + p] = s.z;
    p = atomicAdd(&g_cnt[d.w], 1); g_buck[d.w * CAP + p] = s.w;
}

// ---------------- prescale: g_xsh = fp16(logmap0(x)) -----------------------
__global__ void k_prescale(const float* __restrict__ x) {
    int node = blockIdx.x * 8 + (threadIdx.x >> 5);
    int lane = threadIdx.x & 31;
    const float* row = x + (size_t)node * (FT_IN + 1);
    float v[8];
    float ss = 0.f;
    #pragma unroll
    for (int q = 0; q < 8; q++) {
        v[q] = row[1 + lane + 32 * q];
        ss += v[q] * v[q];
    }
    ss = warp_sum(ss);
    float x0 = fmaxf(row[0], 1.0f + EPSV);
    float r  = acoshf(x0) / fmaxf(sqrtf(ss), EPSV);
    uint32_t* orow = g_xsh + (size_t)node * (FT_IN / 2);
    #pragma unroll
    for (int q = 0; q < 8; q++) {
        float sv = r * v[q];
        float ov = __shfl_xor_sync(0xFFFFFFFFu, sv, 1);
        if ((lane & 1) == 0)
            orow[(lane >> 1) + 16 * q] = pack_h2(sv, ov);
    }
}

// ---------- fp16 MMA GEMM (double-buffered) + fused attention scores -------
// A: packed fp16 k-pairs (g_xsh layer 1, g_th layer 2). Z = A@W + b.
// Emits Z in fp32 (g_z gather table) and g_ssrc/g_sdst (fp32).
template <int K>
__global__ void k_gemm(const float* __restrict__ W,
                       const float* __restrict__ bias,
                       const float* __restrict__ asrc,
                       const float* __restrict__ adst) {
    __shared__ uint32_t As2[2][128][12];  // [m][k2] pairs, pad 12 (conflict-free)
    __shared__ uint32_t Bs2[2][8][136];   // [k2][n] pairs, pad 136
    __shared__ float    Ssrc[128];
    __shared__ float    Sdst[128];
    const uint32_t* Ax = (K == FT_IN) ? g_xsh : g_th;
    int t    = threadIdx.x;
    int m0   = blockIdx.x * 128;
    int lane = t & 31, warp = t >> 5;
    int wm = (warp & 3) * 32;          // warp row offset
    int wn = (warp >> 2) * 64;         // warp col offset
    int g  = lane >> 2, tg = lane & 3;

    if (t < 128) { Ssrc[t] = 0.f; Sdst[t] = 0.f; }

    float acc[2][8][4];
    #pragma unroll
    for (int mi = 0; mi < 2; mi++)
        #pragma unroll
        for (int nj = 0; nj < 8; nj++)
            #pragma unroll
            for (int q = 0; q < 4; q++) acc[mi][nj][q] = 0.f;

    int la_m = t >> 1, la_ku = (t & 1) * 4;
    int k2b = t >> 5, nb = (t & 31) * 4;
    const uint32_t* apRow = Ax + (size_t)(m0 + la_m) * (K / 2) + la_ku;

    // preload tile 0
    {
        uint4 av = *(const uint4*)apRow;
        *(uint4*)&As2[0][la_m][la_ku] = av;
        float4 w0 = *(const float4*)(W + (size_t)(2 * k2b) * HID + nb);
        float4 w1 = *(const float4*)(W + (size_t)(2 * k2b + 1) * HID + nb);
        uint32_t* pb = &Bs2[0][k2b][nb];
        pb[0] = pack_h2(w0.x, w1.x);
        pb[1] = pack_h2(w0.y, w1.y);
        pb[2] = pack_h2(w0.z, w1.z);
        pb[3] = pack_h2(w0.w, w1.w);
    }
    __syncthreads();

    const int NT = K / 16;             // tiles
    for (int kt = 0; kt < NT; kt++) {
        int  buf  = kt & 1;
        bool more = (kt + 1) < NT;
        uint4 na; float4 nw0, nw1;
        if (more) {
            na  = *(const uint4*)(apRow + (kt + 1) * 8);
            int kbase = (kt + 1) * 16;
            nw0 = *(const float4*)(W + (size_t)(kbase + 2 * k2b) * HID + nb);
            nw1 = *(const float4*)(W + (size_t)(kbase + 2 * k2b + 1) * HID + nb);
        }
        uint32_t bf0[8], bf1[8];
        #pragma unroll
        for (int nj = 0; nj < 8; nj++) {
            bf0[nj] = Bs2[buf][tg][wn + nj * 8 + g];
            bf1[nj] = Bs2[buf][tg + 4][wn + nj * 8 + g];
        }
        #pragma unroll
        for (int mi = 0; mi < 2; mi++) {
            int r = wm + mi * 16 + g;
            uint32_t a0 = As2[buf][r][tg];
            uint32_t a1 = As2[buf][r + 8][tg];
            uint32_t a2 = As2[buf][r][tg + 4];
            uint32_t a3 = As2[buf][r + 8][tg + 4];
            #pragma unroll
            for (int nj = 0; nj < 8; nj++)
                mma_f16(acc[mi][nj], a0, a1, a2, a3, bf0[nj], bf1[nj]);
        }
        if (more) {
            *(uint4*)&As2[buf ^ 1][la_m][la_ku] = na;
            uint32_t* pb = &Bs2[buf ^ 1][k2b][nb];
            pb[0] = pack_h2(nw0.x, nw1.x);
            pb[1] = pack_h2(nw0.y, nw1.y);
            pb[2] = pack_h2(nw0.z, nw1.z);
            pb[3] = pack_h2(nw0.w, nw1.w);
        }
        __syncthreads();
    }

    // epilogue: z = acc + bias (fp32) -> g_z (float2 stores), scores fp32
    int rows[4] = { wm + g, wm + g + 8, wm + 16 + g, wm + 24 + g };
    float ps[4] = {0.f, 0.f, 0.f, 0.f};
    float pd[4] = {0.f, 0.f, 0.f, 0.f};
    #pragma unroll
    for (int nj = 0; nj < 8; nj++) {
        int c = wn + nj * 8 + 2 * tg;
        float b0 = bias[c], b1 = bias[c + 1];
        float s0 = asrc[c], s1 = asrc[c + 1];
        float d0 = adst[c], d1 = adst[c + 1];
        #pragma unroll
        for (int mi = 0; mi < 2; mi++) {
            float v00 = acc[mi][nj][0] + b0;
            float v01 = acc[mi][nj][1] + b1;
            float v10 = acc[mi][nj][2] + b0;
            float v11 = acc[mi][nj][3] + b1;
            *(float2*)(g_z + (size_t)(m0 + rows[mi * 2]) * HID + c)
                = make_float2(v00, v01);
            *(float2*)(g_z + (size_t)(m0 + rows[mi * 2 + 1]) * HID + c)
                = make_float2(v10, v11);
            ps[mi * 2]     += v00 * s0 + v01 * s1;
            ps[mi * 2 + 1] += v10 * s0 + v11 * s1;
            pd[mi * 2]     += v00 * d0 + v01 * d1;
            pd[mi * 2 + 1] += v10 * d0 + v11 * d1;
        }
    }
    #pragma unroll
    for (int i = 0; i < 4; i++) {
        atomicAdd(&Ssrc[rows[i]], ps[i]);
        atomicAdd(&Sdst[rows[i]], pd[i]);
    }
    __syncthreads();
    if (t < 128) {
        g_ssrc[m0 + t] = Ssrc[t];
        g_sdst[m0 + t] = Sdst[t];
    }
}

// ---------------- fused GAT aggregation + post-processing -------------------
// One warp per node; lane l owns channels [4l, 4l+4).
// Issue-bound optimization: fp32 z rows loaded as ulonglong2 (two f32x2
// halves), accumulated with packed fma.rn.f32x2. Padded 4-wide loop (w=0
// slots), no tail branch. exp computed once per edge by its owning lane.
//  MODE 0: g = gelu(logmap0(projx(expmap0(u))))  -> g_th (fp16 tangent)
//  MODE 1: h = projx(expmap0(u))                 -> g_h2
template <int MODE>
__global__ void k_gat() {
    int node = blockIdx.x * 8 + (threadIdx.x >> 5);
    int lane = threadIdx.x & 31;
    int cnt = g_cnt[node];
    int beg = node * CAP;
    int end = beg + cnt;
    float sdst = g_sdst[node];
    unsigned long long accXY = 0ull, accZW = 0ull;   // {0.f,0.f} bit pattern
    float denp = 0.f;

    for (int base = beg; base < end; base += 32) {
        int m = end - base; if (m > 32) m = 32;
        int sid = 0; float w = 0.f;
        if (lane < m) {
            sid = g_buck[base + lane];
            float sc = sdst + g_ssrc[sid];
            sc = fmaxf(sc, 0.2f * sc);               // leaky_relu 0.2
            w = __expf(sc);
        }
        denp += w;
        int m4 = (m + 3) & ~3;                       // padded: w=0 slots inert
        for (int j = 0; j < m4; j += 4) {
            int s0 = __shfl_sync(0xFFFFFFFFu, sid, j);
            int s1 = __shfl_sync(0xFFFFFFFFu, sid, j + 1);
            int s2 = __shfl_sync(0xFFFFFFFFu, sid, j + 2);
            int s3 = __shfl_sync(0xFFFFFFFFu, sid, j + 3);
            float w0 = __shfl_sync(0xFFFFFFFFu, w, j);
            float w1 = __shfl_sync(0xFFFFFFFFu, w, j + 1);
            float w2 = __shfl_sync(0xFFFFFFFFu, w, j + 2);
            float w3 = __shfl_sync(0xFFFFFFFFu, w, j + 3);
            ulonglong2 q0 = ((const ulonglong2*)(g_z + (size_t)s0 * HID))[lane];
            ulonglong2 q1 = ((const ulonglong2*)(g_z + (size_t)s1 * HID))[lane];
            ulonglong2 q2 = ((const ulonglong2*)(g_z + (size_t)s2 * HID))[lane];
            ulonglong2 q3 = ((const ulonglong2*)(g_z + (size_t)s3 * HID))[lane];
            unsigned long long W0 = dupw(w0), W1 = dupw(w1);
            unsigned long long W2 = dupw(w2), W3 = dupw(w3);
            fma_x2(accXY, q0.x, W0); fma_x2(accZW, q0.y, W0);
            fma_x2(accXY, q1.x, W1); fma_x2(accZW, q1.y, W1);
            fma_x2(accXY, q2.x, W2); fma_x2(accZW, q2.y, W2);
            fma_x2(accXY, q3.x, W3); fma_x2(accZW, q3.y, W3);
        }
    }
    float den = warp_sum(denp);

    float axy[2], azw[2];
    asm("mov.b64 {%0, %1}, %2;" : "=f"(axy[0]), "=f"(axy[1]) : "l"(accXY));
    asm("mov.b64 {%0, %1}, %2;" : "=f"(azw[0]), "=f"(azw[1]) : "l"(accZW));

    float dn = fmaxf(den, EPSV);
    float u[4] = { axy[0] / dn, axy[1] / dn, azw[0] / dn, azw[1] / dn };
    float ss = u[0]*u[0] + u[1]*u[1] + u[2]*u[2] + u[3]*u[3];
    ss = warp_sum(ss);
    float n    = sqrtf(ss);
    float coef = (n < EPSV) ? 1.0f : (sinhf(n) / n);      // expmap0 spatial

    float xs_n2 = coef * coef * ss;
    if (MODE == 1) {
        float* hr = g_h2 + (size_t)node * DHID;
        if (lane == 0) hr[0] = sqrtf(1.0f + xs_n2);
        #pragma unroll
        for (int q = 0; q < 4; q++) hr[1 + lane * 4 + q] = coef * u[q];
        return;
    }
    // MODE 0: projx -> logmap0 -> gelu, store fp16 tangent (expmap0 cancels
    // against layer-2's logmap0 exactly)
    float x0p = sqrtf(1.0f + xs_n2);
    float xsn = sqrtf(xs_n2);
    float sc2 = acoshf(fmaxf(x0p, 1.0f + EPSV)) / fmaxf(xsn, EPSV);
    float gv0 = gelu_tanh(sc2 * coef * u[0]);
    float gv1 = gelu_tanh(sc2 * coef * u[1]);
    float gv2 = gelu_tanh(sc2 * coef * u[2]);
    float gv3 = gelu_tanh(sc2 * coef * u[3]);
    uint2 pk;
    pk.x = pack_h2(gv0, gv1);
    pk.y = pack_h2(gv2, gv3);
    ((uint2*)(g_th + (size_t)node * (HID / 2)))[lane] = pk;
}

// --------- fused centroid + head (one block per batch graph) ----------------
__global__ void k_readout(const float* __restrict__ Wl,
                          const float* __restrict__ lin_scale,
                          float* __restrict__ out) {
    int b = blockIdx.x;
    int t = threadIdx.x;
    int warp = t >> 5, lane = t & 31;
    __shared__ float accs[8][DHID + 3];    // per-warp column partials (padded)
    __shared__ float ave[DHID];
    __shared__ float gsh[DHID];
    __shared__ float red[3];

    const float* base = g_h2 + (size_t)b * NPB * DHID;
    float ra[5] = {0.f, 0.f, 0.f, 0.f, 0.f};
    for (int r = warp; r < NPB; r += 8) {
        const float* row = base + (size_t)r * DHID;
        #pragma unroll
        for (int q = 0; q < 5; q++) {
            int c = lane + 32 * q;
            if (c < DHID) ra[q] += row[c];
        }
    }
    #pragma unroll
    for (int q = 0; q < 5; q++) {
        int c = lane + 32 * q;
        if (c < DHID) accs[warp][c] = ra[q];
    }
    __syncthreads();
    if (t < DHID) {
        float s = 0.f;
        #pragma unroll
        for (int w = 0; w < 8; w++) s += accs[w][t];
        ave[t] = s * (1.0f / (float)NPB);
        gsh[t] = base[t];                  // node b*512 row (for head)
    }
    __syncthreads();

    if (t == 0) {
        float inner = 0.f;
        #pragma unroll 4
        for (int c = 1; c < DHID; c++) inner += ave[c] * ave[c];
        inner -= ave[0] * ave[0];
        red[0] = sqrtf(fmaxf(-inner, 1e-8f));
    }
    __syncthreads();
    if (t < DHID)
        out[BATCH * DHID + b * DHID + t] = ave[t] / red[0];

    // ---- head ----
    float y = 0.f;
    if (t < DHID) {
        #pragma unroll 4
        for (int k = 0; k < DHID; k++) y += gsh[k] * Wl[k * DHID + t];
    }
    if (t == 0) { red[1] = y; red[2] = 0.f; }
    __syncthreads();
    if (t >= 1 && t < DHID) atomicAdd(&red[2], y * y);
    __syncthreads();
    if (t < DHID) {
        float tt  = 1.0f / (1.0f + expf(-red[1])) * lin_scale[0] + 1.1f;
        float fac = sqrtf((tt * tt - 1.0f) / fmaxf(red[2], 1e-8f));
        out[b * DHID + t] = (t == 0) ? tt : y * fac;
    }
}

// ---------------- launch ----------------------------------------------------
extern "C" void kernel_launch(void* const* d_in, const int* in_sizes, int n_in,
                              void* d_out, int out_size) {
    int idx = 0;
    const float* x  = (const float*)d_in[idx++];   // (32768, 257)
    const int*   ei = (const int*)d_in[idx++];     // (2, 524288)
    if (idx < n_in && in_sizes[idx] == 1) idx++;   // batch_size scalar, if present
    const float* W1  = (const float*)d_in[idx++];
    const float* b1  = (const float*)d_in[idx++];
    const float* a1s = (const float*)d_in[idx++];
    const float* a1d = (const float*)d_in[idx++];
    const float* W2  = (const float*)d_in[idx++];
    const float* b2  = (const float*)d_in[idx++];
    const float* a2s = (const float*)d_in[idx++];
    const float* a2d = (const float*)d_in[idx++];
    const float* Wl  = (const float*)d_in[idx++];
    const float* ls  = (const float*)d_in[idx++];
    float* out = (float*)d_out;

    // side stream + events + symbol addr, created once (first call is the
    // uncaptured correctness run; capture replays see only the recorded DAG)
    static cudaStream_t s2 = 0;
    static cudaEvent_t evFork = 0, evCsr = 0;
    static void* cntPtr = 0;
    if (!s2) {
        cudaStreamCreateWithFlags(&s2, cudaStreamNonBlocking);
        cudaEventCreateWithFlags(&evFork, cudaEventDisableTiming);
        cudaEventCreateWithFlags(&evCsr, cudaEventDisableTiming);
        cudaGetSymbolAddress(&cntPtr, g_cnt);
    }

    // fork point for the side stream (before any work on stream 0)
    cudaEventRecord(evFork, 0);
    cudaStreamWaitEvent(s2, evFork, 0);

    // ---- one-pass bucket build on side stream (overlaps prescale+GEMM1) ----
    cudaMemsetAsync(cntPtr, 0, N_NODES * sizeof(int), s2);
    k_scatter<<<N_EDGES / 4 / 256, 256, 0, s2>>>(ei);
    cudaEventRecord(evCsr, s2);

    // ---- layer 1: prescale (logmap0 -> fp16 buffer), then fp16 GEMM ----
    k_prescale<<<N_NODES / 8, 256>>>(x);
    k_gemm<FT_IN><<<N_NODES / 128, 256>>>(W1, b1, a1s, a1d);
    cudaStreamWaitEvent(0, evCsr, 0);
    k_gat<0><<<N_NODES / 8, 256>>>();

    // ---- layer 2 (A = fp16 tangent buffer) ----
    k_gemm<HID><<<N_NODES / 128, 256>>>(W2, b2, a2s, a2d);
    k_gat<1><<<N_NODES / 8, 256>>>();

    // ---- readout (centroid + head fused) ----
    k_readout<<<BATCH, 256>>>(Wl, ls, out);
}